// round 1
// baseline (speedup 1.0000x reference)
#include <cuda_runtime.h>

// TT-layer: out[n,a,b,c,d] = relu( sum_{i,j,k,l,r,s,t} x[n,i,j,k,l] G1[a,i,r]
//                                  G2[b,j,r,s] G3[c,k,s,t] G4[d,l,t] + bias[a,b,c,d] )
// S=16, R=4, B=1024.
//
// Chain contraction in two fused kernels:
//   k1: per sample n, per kl-tile (16 cols): contract i (G1), then (j,r) (G2)
//       -> U[n][ab][s*256 + kl]   (1 GB scratch, __device__ global)
//   k2: per sample n, per ab-tile (8 pairs): contract (k,s) (G3), then (l,t) (G4)
//       -> out, + bias, relu.

__device__ float g_U[268435456]; // [n=1024][ab=256][skl=1024] = 1 GiB scratch

__global__ __launch_bounds__(256) void tt_k1(const float* __restrict__ x,
                                             const float* __restrict__ G1,
                                             const float* __restrict__ G2,
                                             int nb) {
  extern __shared__ float sm[];
  float* G1s = sm;           // [ar=64][i=16]            1024 f
  float* G2s = sm + 1024;    // [jr=64][bs=64]           4096 f
  float* xs  = sm + 5120;    // [ij=256][c=16 pad 17]    4352 f
  float* T1s = sm + 9472;    // [ar=64][j=16][c pad 17] 17408 f
  const int t = threadIdx.x;
  const int n = blockIdx.x;
  if (n >= nb) return;

  // Stage G1: G1s[(a*4+r)*16 + i] = G1[a,i,r]
  for (int idx = t; idx < 1024; idx += 256) {
    int ar = idx >> 4, i = idx & 15;
    G1s[idx] = G1[(((ar >> 2) * 16 + i) << 2) + (ar & 3)];
  }
  // Stage G2: G2s[(j*4+r)*64 + (b*4+s)] = G2[b,j,r,s]
  for (int idx = t; idx < 4096; idx += 256) {
    int jr = idx >> 6, bs = idx & 63;
    int j = jr >> 2, r = jr & 3, b = bs >> 2, s = bs & 3;
    G2s[idx] = G2[(((b * 16 + j) * 4 + r) << 2) + s];
  }

  const float* xn = x + (size_t)n * 65536;
  const int c  = t & 15;   // column within tile
  const int hi = t >> 4;   // j in phase A, a in phase B
  __syncthreads();

  for (int tile = 0; tile < 16; ++tile) {
    const int col0 = tile * 16;
    // Load x tile: xs[ij][c] ; warp reads two 64B segments per iter (coalesced)
    #pragma unroll
    for (int rep = 0; rep < 16; ++rep) {
      int ij = rep * 16 + hi;
      xs[ij * 17 + c] = xn[ij * 256 + col0 + c];
    }
    __syncthreads();

    // Phase A: T1[a,r,j,c] = sum_i x[i,j,c] * G1[a,i,r]    (thread = (j=hi, c))
    {
      float acc[64];
      #pragma unroll
      for (int q = 0; q < 64; ++q) acc[q] = 0.f;
      for (int i = 0; i < 16; ++i) {
        float xv = xs[(i * 16 + hi) * 17 + c];
        #pragma unroll
        for (int ar = 0; ar < 64; ++ar) acc[ar] += G1s[ar * 16 + i] * xv;
      }
      #pragma unroll
      for (int ar = 0; ar < 64; ++ar) T1s[(ar * 16 + hi) * 17 + c] = acc[ar];
    }
    __syncthreads();

    // Phase B: U[a,b,s,c] = sum_{j,r} T1[a,r,j,c] * G2[b,j,r,s]  (thread = (a=hi, c))
    {
      float acc[64];
      #pragma unroll
      for (int q = 0; q < 64; ++q) acc[q] = 0.f;
      for (int jr = 0; jr < 64; ++jr) {
        int j = jr >> 2, r = jr & 3;
        float v = T1s[((hi * 4 + r) * 16 + j) * 17 + c];
        #pragma unroll
        for (int bs = 0; bs < 64; ++bs) acc[bs] += v * G2s[jr * 64 + bs];
      }
      float* Ub = g_U + ((size_t)n * 256 + hi * 16) * 1024 + col0 + c;
      #pragma unroll
      for (int bs = 0; bs < 64; ++bs)
        Ub[(size_t)(bs >> 2) * 1024 + (bs & 3) * 256] = acc[bs];
    }
    __syncthreads();
  }
}

__global__ __launch_bounds__(256) void tt_k2(const float* __restrict__ G3,
                                             const float* __restrict__ G4,
                                             const float* __restrict__ bias,
                                             float* __restrict__ out,
                                             int nb) {
  extern __shared__ float sm[];
  float* G3s = sm;            // [sk=64][ct=64]            4096 f
  float* G4s = sm + 4096;     // [tl=64][d=16]             1024 f
  float* Us  = sm + 5120;     // [p=8][sk=64][l pad 17]    8704 f
  float* T3s = sm + 13824;    // [p=8][ct=64][l pad 17]    8704 f
  const int t = threadIdx.x;
  const int n = blockIdx.x;
  if (n >= nb) return;

  // G3s[(s*16+k)*64 + (c*4+t)] = G3[c,k,s,t]
  for (int idx = t; idx < 4096; idx += 256) {
    int sk = idx >> 6, ct = idx & 63;
    int s = sk >> 4, k = sk & 15, cc = ct >> 2, tt = ct & 3;
    G3s[idx] = G3[(((cc * 16 + k) * 4 + s) << 2) + tt];
  }
  // G4s[(t*16+l)*16 + d] = G4[d,l,t]
  for (int idx = t; idx < 1024; idx += 256) {
    int tl = idx >> 4, d = idx & 15;
    int tt = tl >> 4, l = tl & 15;
    G4s[idx] = G4[((d * 16 + l) << 2) + tt];
  }
  __syncthreads();

  const int p = t >> 5; // warp index = ab pair within tile

  for (int tile = 0; tile < 32; ++tile) {
    const int ab0 = tile * 8;
    const float* Ug = g_U + ((size_t)n * 256 + ab0) * 1024;
    // Load U tile (8 pairs x 1024 contiguous floats) -> Us[p][sk][l]
    #pragma unroll
    for (int rep = 0; rep < 32; ++rep) {
      int idx = rep * 256 + t;
      int pp = idx >> 10, rem = idx & 1023;
      Us[(pp * 64 + (rem >> 4)) * 17 + (rem & 15)] = Ug[idx];
    }
    __syncthreads();

    // Phase A: T3[p, c,t, l] = sum_{s,k} U[p, s,k, l] * G3[c,k,s,t]
    // thread = (p, h = half of ct range, l)
    {
      const int l = t & 15, h = (t >> 4) & 1;
      float acc[32];
      #pragma unroll
      for (int q = 0; q < 32; ++q) acc[q] = 0.f;
      for (int sk = 0; sk < 64; ++sk) {
        float u = Us[(p * 64 + sk) * 17 + l];
        #pragma unroll
        for (int q = 0; q < 32; ++q) acc[q] += u * G3s[sk * 64 + h * 32 + q];
      }
      #pragma unroll
      for (int q = 0; q < 32; ++q) T3s[(p * 64 + h * 32 + q) * 17 + l] = acc[q];
    }
    __syncthreads();

    // Phase B: out[p, c, d] = relu( sum_{t,l} T3[p, c,t, l] * G4[d,l,t] + bias )
    // thread = (p, c, dh = half of d range)
    {
      const int dh = t & 1, cc = (t >> 1) & 15;
      float acc[8];
      #pragma unroll
      for (int q = 0; q < 8; ++q) acc[q] = 0.f;
      for (int tl = 0; tl < 64; ++tl) {
        int tt = tl >> 4, l = tl & 15;
        float v = T3s[(p * 64 + cc * 4 + tt) * 17 + l];
        #pragma unroll
        for (int q = 0; q < 8; ++q) acc[q] += v * G4s[tl * 16 + dh * 8 + q];
      }
      int abcd = (ab0 + p) * 256 + cc * 16 + dh * 8;
      float* op = out + (size_t)n * 65536 + abcd;
      const float* bp = bias + abcd;
      #pragma unroll
      for (int q = 0; q < 8; ++q) op[q] = fmaxf(acc[q] + bp[q], 0.f);
    }
    __syncthreads();
  }
}

extern "C" void kernel_launch(void* const* d_in, const int* in_sizes, int n_in,
                              void* d_out, int out_size) {
  const float* x    = (const float*)d_in[0];
  const float* G1   = (const float*)d_in[1];
  const float* G2   = (const float*)d_in[2];
  const float* G3   = (const float*)d_in[3];
  const float* G4   = (const float*)d_in[4];
  const float* bias = (const float*)d_in[5];
  float* out = (float*)d_out;

  int nb = in_sizes[0] / 65536; // batch (1024)

  const int smem1 = 26880 * 4; // 107520 B
  const int smem2 = 22528 * 4; //  90112 B
  cudaFuncSetAttribute(tt_k1, cudaFuncAttributeMaxDynamicSharedMemorySize, smem1);
  cudaFuncSetAttribute(tt_k2, cudaFuncAttributeMaxDynamicSharedMemorySize, smem2);

  tt_k1<<<nb, 256, smem1>>>(x, G1, G2, nb);
  tt_k2<<<nb, 256, smem2>>>(G3, G4, bias, out, nb);
}

// round 4
// speedup vs baseline: 1.8955x; 1.8955x over previous
#include <cuda_runtime.h>
#include <cstdint>

// TT layer via merged-core GEMMs on legacy tf32 mma.sync (HMMA path).
// out[n,ab,cd] = relu( sum_{s,ij,kl} H12[ab,(s,ij)] x[n,ij,kl] H34[(cd,s),kl] + bias[ab,cd] )
//   H12[ab][s*256+ij]  = sum_r G1[a,i,r] G2[b,j,r,s]        (256 x 1024)
//   H34[cd*4+s][kl]    = sum_t G3[c,k,s,t] G4[d,l,t]        (1024 x 256)
// GEMM1 per n: M1[cd4s, ij] = H34 . x[n]^T      M=1024 N=256 K=256
// GEMM2 per n: out[ab, cd]  = H12 . M1[n]^T     M=256  N=256 K=1024  (+bias, relu)
// All GEMM operands are RNA-rounded to tf32 BEFORE the GEMM (prep kernels /
// x pre-pass / GEMM1 epilogue), so HMMA's RZ truncation is a no-op and the
// effective rounding is unbiased.

__device__ float g_H34[262144];
__device__ float g_H12[262144];
__device__ float g_Xr[67108864];   // RNA-rounded x, 256 MB
__device__ float g_M1[268435456];  // [n][cd*4+s][ij] fp32 (tf32-exact), 1 GiB

__device__ __forceinline__ float rna_tf32(float f) {
  uint32_t r;
  asm("cvt.rna.tf32.f32 %0, %1;" : "=r"(r) : "f"(f));
  return __uint_as_float(r);
}

// ---------------- precompute ----------------
__global__ void prep_h34(const float* __restrict__ G3, const float* __restrict__ G4) {
  int e = blockIdx.x * 256 + threadIdx.x;
  int col = e & 255, row = e >> 8;
  int s = row & 3, cd = row >> 2;
  int c = cd >> 4, d = cd & 15, k = col >> 4, l = col & 15;
  float acc = 0.f;
#pragma unroll
  for (int tt = 0; tt < 4; ++tt)
    acc += G3[((c * 16 + k) * 4 + s) * 4 + tt] * G4[(d * 16 + l) * 4 + tt];
  g_H34[e] = rna_tf32(acc);
}
__global__ void prep_h12(const float* __restrict__ G1, const float* __restrict__ G2) {
  int e = blockIdx.x * 256 + threadIdx.x;
  int ab = e >> 10, rem = e & 1023;
  int s = rem >> 8, ij = rem & 255;
  int a = ab >> 4, b = ab & 15, i = ij >> 4, j = ij & 15;
  float acc = 0.f;
#pragma unroll
  for (int r = 0; r < 4; ++r)
    acc += G1[(a * 16 + i) * 4 + r] * G2[((b * 16 + j) * 4 + r) * 4 + s];
  g_H12[e] = rna_tf32(acc);
}
__global__ __launch_bounds__(256) void round_x(const float* __restrict__ x) {
  int idx = blockIdx.x * 256 + threadIdx.x;  // one float4 per thread
  float4 v = *(const float4*)(x + (size_t)idx * 4);
  v.x = rna_tf32(v.x); v.y = rna_tf32(v.y);
  v.z = rna_tf32(v.z); v.w = rna_tf32(v.w);
  *(float4*)(g_Xr + (size_t)idx * 4) = v;
}

// ---------------- helpers ----------------
__device__ __forceinline__ uint32_t smem_u32(const void* p) {
  uint32_t a;
  asm("{ .reg .u64 t; cvta.to.shared.u64 t, %1; cvt.u32.u64 %0, t; }" : "=r"(a) : "l"(p));
  return a;
}
__device__ __forceinline__ void cp16(uint32_t s, const float* g) {
  asm volatile("cp.async.cg.shared.global [%0], [%1], 16;" :: "r"(s), "l"(g));
}
__device__ __forceinline__ void mma_tf32(float* c, const uint32_t* a, const uint32_t* b) {
  asm volatile(
      "mma.sync.aligned.m16n8k8.row.col.f32.tf32.tf32.f32 "
      "{%0,%1,%2,%3}, {%4,%5,%6,%7}, {%8,%9}, {%0,%1,%2,%3};"
      : "+f"(c[0]), "+f"(c[1]), "+f"(c[2]), "+f"(c[3])
      : "r"(a[0]), "r"(a[1]), "r"(a[2]), "r"(a[3]), "r"(b[0]), "r"(b[1]));
}

// ---------------- generic batched GEMM: C[n] = A . B[n]^T ----------------
// A [Mtotal x K] K-major; B[n] [256 x K] K-major; C[n] [Mtotal x 256] row-major.
// blockIdx.x = mt*2 + nt ; blockIdx.y = n. CTA tile 128x128, 8 warps of 32x64.
// Smem per stage: A 128x36f + B 128x36f (pad 36 -> conflict-free fragments).
#define STG_F 9216  // floats per stage (2 * 128 * 36)

__global__ __launch_bounds__(256, 2) void tt_gemm(
    const float* __restrict__ A, const float* __restrict__ Bbase, long long bStride,
    float* __restrict__ Cbase, long long cStride, int K,
    const float* __restrict__ bias, int roundOut) {
  extern __shared__ float sm[];
  const int t = threadIdx.x;
  const int wid = t >> 5, lane = t & 31;
  const int grp = lane >> 2, tg = lane & 3;
  const int bx = blockIdx.x, n = blockIdx.y;
  const int nt = bx & 1, mt = bx >> 1;

  const float* Am = A + (long long)mt * 128 * K;
  const float* Bn = Bbase + (long long)n * bStride + (long long)nt * 128 * K;

  const int row_ld = t >> 3;
  const int q_ld = t & 7;
  uint32_t smA_st[2], smB_st[2];
  {
    uint32_t base = smem_u32(sm);
    uint32_t off = (uint32_t)(row_ld * 36 + q_ld * 4) * 4u;
    smA_st[0] = base + off;
    smB_st[0] = base + 4608u * 4u + off;
    smA_st[1] = smA_st[0] + STG_F * 4u;
    smB_st[1] = smB_st[0] + STG_F * 4u;
  }

  const int nch = K >> 5;

  float acc[2][8][4];
#pragma unroll
  for (int mi = 0; mi < 2; ++mi)
#pragma unroll
    for (int ni = 0; ni < 8; ++ni)
#pragma unroll
      for (int q = 0; q < 4; ++q) acc[mi][ni][q] = 0.f;

  const int wm = (wid & 3) * 32;
  const int wn = (wid >> 2) * 64;

#pragma unroll
  for (int pch = 0; pch < 2; ++pch) {
    const float* ga = Am + pch * 32;
    const float* gb = Bn + pch * 32;
#pragma unroll
    for (int rep = 0; rep < 4; ++rep) {
      int row = row_ld + rep * 32;
      cp16(smA_st[pch] + rep * 32u * 144u, ga + (long long)row * K + q_ld * 4);
      cp16(smB_st[pch] + rep * 32u * 144u, gb + (long long)row * K + q_ld * 4);
    }
    asm volatile("cp.async.commit_group;" ::: "memory");
  }

  for (int ch = 0; ch < nch; ++ch) {
    const int st = ch & 1;
    asm volatile("cp.async.wait_group 1;" ::: "memory");
    __syncthreads();

    const float* sA = sm + st * STG_F;
    const float* sB = sA + 4608;
#pragma unroll
    for (int kk = 0; kk < 4; ++kk) {
      uint32_t a[2][4], b[8][2];
      const int k0 = kk * 8 + tg;
#pragma unroll
      for (int mi = 0; mi < 2; ++mi) {
        const float* ar = sA + (wm + mi * 16 + grp) * 36;
        a[mi][0] = __float_as_uint(ar[k0]);
        a[mi][1] = __float_as_uint(ar[8 * 36 + k0]);
        a[mi][2] = __float_as_uint(ar[k0 + 4]);
        a[mi][3] = __float_as_uint(ar[8 * 36 + k0 + 4]);
      }
#pragma unroll
      for (int ni = 0; ni < 8; ++ni) {
        const float* br = sB + (wn + ni * 8 + grp) * 36;
        b[ni][0] = __float_as_uint(br[kk * 8 + tg]);
        b[ni][1] = __float_as_uint(br[kk * 8 + tg + 4]);
      }
#pragma unroll
      for (int mi = 0; mi < 2; ++mi)
#pragma unroll
        for (int ni = 0; ni < 8; ++ni) mma_tf32(acc[mi][ni], a[mi], b[ni]);
    }
    __syncthreads();
    if (ch + 2 < nch) {
      const float* ga = Am + (ch + 2) * 32;
      const float* gb = Bn + (ch + 2) * 32;
#pragma unroll
      for (int rep = 0; rep < 4; ++rep) {
        int row = row_ld + rep * 32;
        cp16(smA_st[st] + rep * 32u * 144u, ga + (long long)row * K + q_ld * 4);
        cp16(smB_st[st] + rep * 32u * 144u, gb + (long long)row * K + q_ld * 4);
      }
    }
    asm volatile("cp.async.commit_group;" ::: "memory");
  }

  float* Cn = Cbase + (long long)n * cStride;
#pragma unroll
  for (int mi = 0; mi < 2; ++mi) {
    int r0 = mt * 128 + wm + mi * 16 + grp;
#pragma unroll
    for (int ni = 0; ni < 8; ++ni) {
      int col = nt * 128 + wn + ni * 8 + 2 * tg;
      float v0 = acc[mi][ni][0], v1 = acc[mi][ni][1];
      float v2 = acc[mi][ni][2], v3 = acc[mi][ni][3];
      if (bias) {
        v0 = fmaxf(v0 + bias[r0 * 256 + col], 0.f);
        v1 = fmaxf(v1 + bias[r0 * 256 + col + 1], 0.f);
        v2 = fmaxf(v2 + bias[(r0 + 8) * 256 + col], 0.f);
        v3 = fmaxf(v3 + bias[(r0 + 8) * 256 + col + 1], 0.f);
      } else if (roundOut) {
        v0 = rna_tf32(v0); v1 = rna_tf32(v1);
        v2 = rna_tf32(v2); v3 = rna_tf32(v3);
      }
      *(float2*)(Cn + (long long)r0 * 256 + col) = make_float2(v0, v1);
      *(float2*)(Cn + (long long)(r0 + 8) * 256 + col) = make_float2(v2, v3);
    }
  }
}

// ---------------- launch ----------------
extern "C" void kernel_launch(void* const* d_in, const int* in_sizes, int n_in,
                              void* d_out, int out_size) {
  const float* x    = (const float*)d_in[0];
  const float* G1   = (const float*)d_in[1];
  const float* G2   = (const float*)d_in[2];
  const float* G3   = (const float*)d_in[3];
  const float* G4   = (const float*)d_in[4];
  const float* bias = (const float*)d_in[5];
  float* out = (float*)d_out;
  const int nb = in_sizes[0] / 65536;

  float *pH34, *pH12, *pM1, *pXr;
  cudaGetSymbolAddress((void**)&pH34, g_H34);
  cudaGetSymbolAddress((void**)&pH12, g_H12);
  cudaGetSymbolAddress((void**)&pM1, g_M1);
  cudaGetSymbolAddress((void**)&pXr, g_Xr);

  const int smem = 2 * STG_F * 4;  // 73728 B
  cudaFuncSetAttribute(tt_gemm, cudaFuncAttributeMaxDynamicSharedMemorySize, smem);

  prep_h34<<<1024, 256>>>(G3, G4);
  prep_h12<<<1024, 256>>>(G1, G2);
  round_x<<<(in_sizes[0] / 4 + 255) / 256, 256>>>(x);

  // GEMM1: M1[n] = H34 (1024xK256) . Xr[n]^T   -> grid (8 mtiles * 2 ntiles, nb)
  tt_gemm<<<dim3(16, nb), 256, smem>>>(pH34, pXr, 65536LL, pM1, 262144LL, 256,
                                       nullptr, 1);
  // GEMM2: out[n] = H12 (256xK1024) . M1[n]^T  -> grid (2 mtiles * 2 ntiles, nb)
  tt_gemm<<<dim3(4, nb), 256, smem>>>(pH12, pM1, 262144LL, out, 65536LL, 1024,
                                      bias, 0);
}